// round 14
// baseline (speedup 1.0000x reference)
#include <cuda_runtime.h>
#include <math.h>

#define HW   4096
#define NC1  32
#define NC2  64
#define NFC1 512

// ---------------- scratch (static __device__, no allocation) ----------------
__device__ float  d_M1[NC1 * HW];                  // |FFT2(pad(w1))|     0.5 MB
__device__ float  d_A2[NC2 * HW];                  // layer-2 magnitude     1 MB
__device__ float  d_H[10 * HW];                    // fc2-collapsed       160 KB
__device__ float  d_biasv[10];                     // fc2b + fc2w@fc1b
__device__ int    d_flag;                          // M1-done   (0 at rest)
__device__ int    d_flagA;                         // a2f-done  (0 at rest)
__device__ int    d_flag2;                         // k_g-done  (0 at rest)
__device__ int    d_flag3;                         // out-done  (0 at rest)

// non-RMW poll: plain volatile L2 load (broadcast-served, no atomic ALU)
__device__ __forceinline__ void wait_flag(volatile int* f, int target) {
    while (*f < target) __nanosleep(1000);
}

// ======== L0 k_front: prep [0,524) | A2 w/ spin [524,780), 256 thr ==========
__global__ void __launch_bounds__(256) k_front(
        const float* __restrict__ w1r, const float* __restrict__ w1i,
        const float* __restrict__ w2r, const float* __restrict__ w2i,
        const float* __restrict__ fc2w, const float* __restrict__ fc1b,
        const float* __restrict__ fc2b, float* __restrict__ out) {
    __shared__ __align__(16) char sbuf[21504];
    const int bx = blockIdx.x;
    const int tx = threadIdx.x;

    if (bx < 512) {
        // ---- M1[i,hw] = |sum_{a,b} w1[i,a,b] tw(ua+vb)| ----
        float* twr = (float*)sbuf;
        float* twi = twr + 64;
        float* wr  = twi + 64;
        float* wi  = wr + 32;
        if (tx < 64) {
            float s, c;
            sincosf(-6.283185307179586f * (float)tx / 64.0f, &s, &c);
            twr[tx] = c; twi[tx] = s;
        }
        const int i = bx >> 4, tile = bx & 15;
        if (tx < 25) { wr[tx] = w1r[i * 25 + tx]; wi[tx] = w1i[i * 25 + tx]; }
        __syncthreads();
        const int hw = tile * 256 + tx;
        const int u = hw >> 6, v = hw & 63;
        float re = 0.f, im = 0.f;
#pragma unroll
        for (int a = 0; a < 5; a++)
#pragma unroll
            for (int b = 0; b < 5; b++) {
                const int idx = (u * a + v * b) & 63;
                const float tr = twr[idx], ti = twi[idx];
                const float r = wr[a * 5 + b], q = wi[a * 5 + b];
                re += r * tr - q * ti;
                im += r * ti + q * tr;
            }
        d_M1[i * HW + hw] = sqrtf(re * re + im * im);
        __syncthreads();
        __threadfence();
        if (tx == 0) atomicAdd(&d_flag, 1);
    } else if (bx == 512) {
        // ---- bias ----
        const int w = tx >> 5, lane = tx & 31;
        for (int c = w; c < 10; c += 8) {
            float s = 0.f;
            for (int f = lane; f < NFC1; f += 32)
                s += fc2w[c * NFC1 + f] * fc1b[f];
#pragma unroll
            for (int off = 16; off > 0; off >>= 1)
                s += __shfl_down_sync(0xffffffffu, s, off);
            if (lane == 0) d_biasv[c] = s + fc2b[c];
        }
    } else if (bx < 523) {
        const int base = (bx - 513) * 4096;
#pragma unroll
        for (int k = 0; k < 16; k++) d_H[base + k * 256 + tx] = 0.f;
    } else if (bx == 523) {
        for (int i = tx; i < 320; i += 256) out[i] = 0.f;
    } else {
        // ---- A2 role (4-fold twiddle symmetry); volatile-poll on M1 -------
        const int idx = bx - 524;
        const int bxu = idx & 3, o = idx >> 2;
        float2* Ts = (float2*)sbuf;                   // 20480 B
        float* twr = (float*)(sbuf + 20480);
        float* twi = twr + 64;
        if (tx == 0) wait_flag(&d_flag, 512);
        __syncthreads();
        __threadfence();
        if (tx < 64) {
            float s, c;
            sincosf(-6.283185307179586f * (float)tx / 64.0f, &s, &c);
            twr[tx] = c; twi[tx] = s;
        }
        __syncthreads();
        const int du = tx >> 6, v = tx & 63;
        const int u0 = bxu * 4 + du;
        float tur[5], tui[5];
#pragma unroll
        for (int a = 0; a < 5; a++) {
            const int k = (u0 * a) & 63;
            tur[a] = twr[k]; tui[a] = twi[k];
        }
        float re0 = 0.f, im0 = 0.f, re1 = 0.f, im1 = 0.f;
        float re2 = 0.f, im2 = 0.f, re3 = 0.f, im3 = 0.f;
        const int hwb = u0 * 64 + v;
        for (int c = 0; c < 4; c++) {
            __syncthreads();
            for (int i2 = tx; i2 < 8 * 320; i2 += 256) {
                const int ii = i2 / 320;
                const int r = i2 - ii * 320;
                const int a = r >> 6, vv = r & 63;
                const int oi = o * NC1 + c * 8 + ii;
                float re = 0.f, im = 0.f;
#pragma unroll
                for (int b = 0; b < 5; b++) {
                    const int k = (vv * b) & 63;
                    const float rr = w2r[oi * 25 + a * 5 + b];
                    const float qq = w2i[oi * 25 + a * 5 + b];
                    re += rr * twr[k] - qq * twi[k];
                    im += rr * twi[k] + qq * twr[k];
                }
                Ts[i2] = make_float2(re, im);
            }
            __syncthreads();
#pragma unroll
            for (int ii = 0; ii < 8; ii++) {
                const int ig = c * 8 + ii;
                const float m0 = d_M1[ig * HW + hwb];
                const float m1 = d_M1[ig * HW + hwb + 1024];
                const float m2 = d_M1[ig * HW + hwb + 2048];
                const float m3 = d_M1[ig * HW + hwb + 3072];
                float kr0 = 0.f, ki0 = 0.f, kr1 = 0.f, ki1 = 0.f;
                float kr2 = 0.f, ki2 = 0.f, kr3 = 0.f, ki3 = 0.f;
#pragma unroll
                for (int a = 0; a < 5; a++) {
                    const float2 tt = Ts[ii * 320 + a * 64 + v];
                    const float pr = tur[a] * tt.x - tui[a] * tt.y;
                    const float pi = tur[a] * tt.y + tui[a] * tt.x;
                    kr0 += pr; ki0 += pi;
                    switch (a & 3) {
                        case 0: kr1 += pr; ki1 += pi;
                                kr2 += pr; ki2 += pi;
                                kr3 += pr; ki3 += pi; break;
                        case 1: kr1 += pi; ki1 -= pr;
                                kr2 -= pr; ki2 -= pi;
                                kr3 -= pi; ki3 += pr; break;
                        case 2: kr1 -= pr; ki1 -= pi;
                                kr2 += pr; ki2 += pi;
                                kr3 -= pr; ki3 -= pi; break;
                        case 3: kr1 -= pi; ki1 += pr;
                                kr2 -= pr; ki2 -= pi;
                                kr3 += pi; ki3 -= pr; break;
                    }
                }
                re0 += m0 * kr0; im0 += m0 * ki0;
                re1 += m1 * kr1; im1 += m1 * ki1;
                re2 += m2 * kr2; im2 += m2 * ki2;
                re3 += m3 * kr3; im3 += m3 * ki3;
            }
        }
        d_A2[o * HW + hwb]        = sqrtf(re0 * re0 + im0 * im0);
        d_A2[o * HW + hwb + 1024] = sqrtf(re1 * re1 + im1 * im1);
        d_A2[o * HW + hwb + 2048] = sqrtf(re2 * re2 + im2 * im2);
        d_A2[o * HW + hwb + 3072] = sqrtf(re3 * re3 + im3 * im3);
        __syncthreads();
        if (tx == 0) {
            const int r = atomicAdd(&d_flagA, 1);
            if (r == 255) { atomicExch(&d_flag, 0); atomicExch(&d_flagA, 0); }
        }
    }
}

// ======== L1 k_gout: k_g [0,512) | k_out w/ spin [512,768), 128 thr =========
__global__ void __launch_bounds__(128) k_gout(const float* __restrict__ fc1w,
                                              const float* __restrict__ fc2w,
                                              const float* __restrict__ x,
                                              float* __restrict__ out) {
    __shared__ __align__(16) char sbuf[33344];
    const int bx = blockIdx.x;
    const int t = threadIdx.x;

    if (bx < 512) {
        // ---------------- k_g role: EXACT R10 configuration ----------------
        float4* a2s = (float4*)sbuf;                 // 16 x 128 float4 = 32 KB
        float* fc2s = (float*)(sbuf + 32768);        // [10][8]
        const int tile = bx & 7;
        const int f0 = (bx >> 3) * 8;
        if (t < 80) {
            const int c = t >> 3, f = t & 7;
            fc2s[c * 8 + f] = fc2w[c * NFC1 + f0 + f];
        }
        const float4* __restrict__ a2g = (const float4*)d_A2;
        const float4* __restrict__ w = (const float4*)fc1w;

        float4 acc[8];
#pragma unroll
        for (int f = 0; f < 8; f++) acc[f] = make_float4(0.f, 0.f, 0.f, 0.f);

        for (int oc = 0; oc < 4; oc++) {
            __syncthreads();
            for (int idx = t; idx < 16 * 128; idx += 128) {
                const int o = idx >> 7, j = idx & 127;
                a2s[idx] = a2g[(oc * 16 + o) * 1024 + tile * 128 + j];
            }
            __syncthreads();
#pragma unroll
            for (int o = 0; o < 16; o++) {
                const float4 av = a2s[o * 128 + t];
                const size_t wb = (size_t)(oc * 16 + o) * 1024 + (size_t)tile * 128 + t;
#pragma unroll
                for (int f = 0; f < 8; f++) {
                    const float4 wv = __ldcs(&w[(size_t)(f0 + f) * 65536 + wb]);
                    acc[f].x += av.x * wv.x;
                    acc[f].y += av.y * wv.y;
                    acc[f].z += av.z * wv.z;
                    acc[f].w += av.w * wv.w;
                }
            }
        }
        const int hwb = (tile * 128 + t) * 4;
#pragma unroll
        for (int c = 0; c < 10; c++) {
            float4 h = make_float4(0.f, 0.f, 0.f, 0.f);
#pragma unroll
            for (int f = 0; f < 8; f++) {
                const float s = fc2s[c * 8 + f];
                h.x += s * acc[f].x;
                h.y += s * acc[f].y;
                h.z += s * acc[f].z;
                h.w += s * acc[f].w;
            }
            atomicAdd(reinterpret_cast<float4*>(&d_H[c * HW + hwb]), h);
        }
        __threadfence();
        __syncthreads();
        if (t == 0) atomicAdd(&d_flag2, 1);
    } else {
        // ---------------- k_out role: volatile-poll on k_g -----------------
        float (*red)[128] = (float (*)[128])sbuf;
        const int idx = bx - 512;
        const int chunk = idx & 7, b = idx >> 3;
        if (t == 0) wait_flag(&d_flag2, 512);
        __syncthreads();
        __threadfence();
        const int hw0 = chunk * 512;
        float acc[10];
#pragma unroll
        for (int c = 0; c < 10; c++) acc[c] = 0.f;
#pragma unroll
        for (int k = 0; k < 4; k++) {
            const int hw = hw0 + k * 128 + t;
            const float a = fabsf(x[b * HW + hw]);
#pragma unroll
            for (int c = 0; c < 10; c++) acc[c] += a * d_H[c * HW + hw];
        }
#pragma unroll
        for (int c = 0; c < 10; c++) red[c][t] = acc[c];
        __syncthreads();
        for (int s = 64; s > 0; s >>= 1) {
            if (t < s) {
#pragma unroll
                for (int c = 0; c < 10; c++) red[c][t] += red[c][t + s];
            }
            __syncthreads();
        }
        if (t < 10) {
            float v = red[t][0];
            if (chunk == 0) v += d_biasv[t];
            atomicAdd(&out[b * 10 + t], v);
        }
        __syncthreads();
        if (t == 0) {
            const int r = atomicAdd(&d_flag3, 1);
            if (r == 255) { atomicExch(&d_flag2, 0); atomicExch(&d_flag3, 0); }
        }
    }
}

// ---------------- launch -----------------------------------------------------
extern "C" void kernel_launch(void* const* d_in, const int* in_sizes, int n_in,
                              void* d_out, int out_size) {
    const float* x    = (const float*)d_in[0];
    const float* w1r  = (const float*)d_in[1];
    const float* w1i  = (const float*)d_in[2];
    const float* w2r  = (const float*)d_in[3];
    const float* w2i  = (const float*)d_in[4];
    const float* fc1w = (const float*)d_in[5];
    const float* fc1b = (const float*)d_in[6];
    const float* fc2w = (const float*)d_in[7];
    const float* fc2b = (const float*)d_in[8];
    float* out = (float*)d_out;

    k_front<<<780, 256>>>(w1r, w1i, w2r, w2i, fc2w, fc1b, fc2b, out);
    k_gout <<<768, 128>>>(fc1w, fc2w, x, out);
}

// round 15
// speedup vs baseline: 1.0518x; 1.0518x over previous
#include <cuda_runtime.h>
#include <math.h>

#define HW   4096
#define NC1  32
#define NC2  64
#define NFC1 512

// ---------------- scratch (static __device__, no allocation) ----------------
__device__ float  d_A2[NC2 * HW];                  // layer-2 magnitude     1 MB
__device__ float  d_H[10 * HW];                    // fc2-collapsed       160 KB
__device__ float  d_biasv[10];                     // fc2b + fc2w@fc1b

// ======== L0 k_a2all: A2 [0,256) | bias 256 | zero H [257,267) | out 267 ====
// A2[o,hw] = |sum_i M1[i,hw] * K2[o,i,hw]| with BOTH DFTs done in-block:
//   T1[i,a,v] = sum_b w1c[i,a,b] tw(vb);  M1 = |sum_a tw(ua) T1|
//   Ts[i,a,v] = sum_b w2c[o,i,a,b] tw(vb); K2 = sum_a tw(ua) Ts
// 4-fold u symmetry: tw((u0+16k)a) = tw(u0 a) * (-i)^(a k).
__global__ void __launch_bounds__(256) k_a2all(
        const float* __restrict__ w1r, const float* __restrict__ w1i,
        const float* __restrict__ w2r, const float* __restrict__ w2i,
        const float* __restrict__ fc2w, const float* __restrict__ fc1b,
        const float* __restrict__ fc2b, float* __restrict__ out) {
    __shared__ __align__(16) char sbuf[41472];     // Ts 20480 | T1s 20480 | tw 512
    const int bx = blockIdx.x;
    const int tx = threadIdx.x;

    if (bx >= 256) {
        if (bx == 256) {
            // ---- bias ----
            const int w = tx >> 5, lane = tx & 31;
            for (int c = w; c < 10; c += 8) {
                float s = 0.f;
                for (int f = lane; f < NFC1; f += 32)
                    s += fc2w[c * NFC1 + f] * fc1b[f];
#pragma unroll
                for (int off = 16; off > 0; off >>= 1)
                    s += __shfl_down_sync(0xffffffffu, s, off);
                if (lane == 0) d_biasv[c] = s + fc2b[c];
            }
        } else if (bx < 267) {
            const int base = (bx - 257) * 4096;
#pragma unroll
            for (int k = 0; k < 16; k++) d_H[base + k * 256 + tx] = 0.f;
        } else {
            for (int i = tx; i < 320; i += 256) out[i] = 0.f;
        }
        return;
    }

    // -------------------- A2 role --------------------
    float2* Ts  = (float2*)sbuf;                   // 8 x 320
    float2* T1s = (float2*)(sbuf + 20480);         // 8 x 320
    float* twr = (float*)(sbuf + 40960);           // 64
    float* twi = twr + 64;                         // 64
    const int bxu = bx & 3, o = bx >> 2;
    if (tx < 64) {
        float s, c;
        sincosf(-6.283185307179586f * (float)tx / 64.0f, &s, &c);
        twr[tx] = c; twi[tx] = s;
    }
    __syncthreads();
    const int du = tx >> 6, v = tx & 63;
    const int u0 = bxu * 4 + du;                   // in [0,16)
    float tur[5], tui[5];
#pragma unroll
    for (int a = 0; a < 5; a++) {
        const int k = (u0 * a) & 63;
        tur[a] = twr[k]; tui[a] = twi[k];
    }
    float re0 = 0.f, im0 = 0.f, re1 = 0.f, im1 = 0.f;
    float re2 = 0.f, im2 = 0.f, re3 = 0.f, im3 = 0.f;
    const int hwb = u0 * 64 + v;

    for (int c = 0; c < 4; c++) {                  // i-chunks of 8
        __syncthreads();
        for (int i2 = tx; i2 < 8 * 320; i2 += 256) {
            const int ii = i2 / 320;
            const int r = i2 - ii * 320;
            const int a = r >> 6, vv = r & 63;
            const int ig = c * 8 + ii;
            const int oi = o * NC1 + ig;
            float re = 0.f, im = 0.f, re1l = 0.f, im1l = 0.f;
#pragma unroll
            for (int b = 0; b < 5; b++) {
                const int k = (vv * b) & 63;
                const float tr = twr[k], ti = twi[k];
                const float rr = w2r[oi * 25 + a * 5 + b];
                const float qq = w2i[oi * 25 + a * 5 + b];
                re += rr * tr - qq * ti;
                im += rr * ti + qq * tr;
                const float r1 = w1r[ig * 25 + a * 5 + b];
                const float q1 = w1i[ig * 25 + a * 5 + b];
                re1l += r1 * tr - q1 * ti;
                im1l += r1 * ti + q1 * tr;
            }
            Ts[i2]  = make_float2(re, im);
            T1s[i2] = make_float2(re1l, im1l);
        }
        __syncthreads();
#pragma unroll
        for (int ii = 0; ii < 8; ii++) {
            float kr0 = 0.f, ki0 = 0.f, kr1 = 0.f, ki1 = 0.f;
            float kr2 = 0.f, ki2 = 0.f, kr3 = 0.f, ki3 = 0.f;
            float mr0 = 0.f, mi0 = 0.f, mr1 = 0.f, mi1 = 0.f;
            float mr2 = 0.f, mi2 = 0.f, mr3 = 0.f, mi3 = 0.f;
#pragma unroll
            for (int a = 0; a < 5; a++) {
                const float2 tt = Ts[ii * 320 + a * 64 + v];
                const float2 t1 = T1s[ii * 320 + a * 64 + v];
                const float pr = tur[a] * tt.x - tui[a] * tt.y;
                const float pi = tur[a] * tt.y + tui[a] * tt.x;
                const float qr = tur[a] * t1.x - tui[a] * t1.y;
                const float qi = tur[a] * t1.y + tui[a] * t1.x;
                kr0 += pr; ki0 += pi; mr0 += qr; mi0 += qi;
                switch (a & 3) {
                    case 0: kr1 += pr; ki1 += pi; mr1 += qr; mi1 += qi;
                            kr2 += pr; ki2 += pi; mr2 += qr; mi2 += qi;
                            kr3 += pr; ki3 += pi; mr3 += qr; mi3 += qi; break;
                    case 1: kr1 += pi; ki1 -= pr; mr1 += qi; mi1 -= qr;
                            kr2 -= pr; ki2 -= pi; mr2 -= qr; mi2 -= qi;
                            kr3 -= pi; ki3 += pr; mr3 -= qi; mi3 += qr; break;
                    case 2: kr1 -= pr; ki1 -= pi; mr1 -= qr; mi1 -= qi;
                            kr2 += pr; ki2 += pi; mr2 += qr; mi2 += qi;
                            kr3 -= pr; ki3 -= pi; mr3 -= qr; mi3 -= qi; break;
                    case 3: kr1 -= pi; ki1 += pr; mr1 -= qi; mi1 += qr;
                            kr2 -= pr; ki2 -= pi; mr2 -= qr; mi2 -= qi;
                            kr3 += pi; ki3 -= pr; mr3 += qi; mi3 -= qr; break;
                }
            }
            const float m0 = sqrtf(mr0 * mr0 + mi0 * mi0);
            const float m1 = sqrtf(mr1 * mr1 + mi1 * mi1);
            const float m2 = sqrtf(mr2 * mr2 + mi2 * mi2);
            const float m3 = sqrtf(mr3 * mr3 + mi3 * mi3);
            re0 += m0 * kr0; im0 += m0 * ki0;
            re1 += m1 * kr1; im1 += m1 * ki1;
            re2 += m2 * kr2; im2 += m2 * ki2;
            re3 += m3 * kr3; im3 += m3 * ki3;
        }
    }
    d_A2[o * HW + hwb]        = sqrtf(re0 * re0 + im0 * im0);
    d_A2[o * HW + hwb + 1024] = sqrtf(re1 * re1 + im1 * im1);
    d_A2[o * HW + hwb + 2048] = sqrtf(re2 * re2 + im2 * im2);
    d_A2[o * HW + hwb + 3072] = sqrtf(re3 * re3 + im3 * im3);
}

// ---------------- L1 (dominant): stream fc1_w — EXACT R10 configuration -----
__global__ void __launch_bounds__(128) k_g(const float* __restrict__ fc1w,
                                           const float* __restrict__ fc2w) {
    __shared__ float4 a2s[16 * 128];              // 16 o-rows x 512 hw = 32 KB
    __shared__ float fc2s[10][8];
    const int t = threadIdx.x;
    const int tile = blockIdx.x;                  // 8 tiles of 512 hw
    const int f0 = blockIdx.y * 8;                // 64 f-chunks of 8
    if (t < 80) {
        const int c = t >> 3, f = t & 7;
        fc2s[c][f] = fc2w[c * NFC1 + f0 + f];
    }
    const float4* __restrict__ a2g = (const float4*)d_A2;
    const float4* __restrict__ w = (const float4*)fc1w;

    float4 acc[8];
#pragma unroll
    for (int f = 0; f < 8; f++) acc[f] = make_float4(0.f, 0.f, 0.f, 0.f);

    for (int oc = 0; oc < 4; oc++) {
        __syncthreads();
        for (int idx = t; idx < 16 * 128; idx += 128) {
            const int o = idx >> 7, j = idx & 127;
            a2s[idx] = a2g[(oc * 16 + o) * 1024 + tile * 128 + j];
        }
        __syncthreads();
#pragma unroll
        for (int o = 0; o < 16; o++) {
            const float4 av = a2s[o * 128 + t];
            const size_t wb = (size_t)(oc * 16 + o) * 1024 + (size_t)tile * 128 + t;
#pragma unroll
            for (int f = 0; f < 8; f++) {
                const float4 wv = __ldcs(&w[(size_t)(f0 + f) * 65536 + wb]);
                acc[f].x += av.x * wv.x;
                acc[f].y += av.y * wv.y;
                acc[f].z += av.z * wv.z;
                acc[f].w += av.w * wv.w;
            }
        }
    }
    const int hwb = (tile * 128 + t) * 4;
#pragma unroll
    for (int c = 0; c < 10; c++) {
        float4 h = make_float4(0.f, 0.f, 0.f, 0.f);
#pragma unroll
        for (int f = 0; f < 8; f++) {
            const float s = fc2s[c][f];
            h.x += s * acc[f].x;
            h.y += s * acc[f].y;
            h.z += s * acc[f].z;
            h.w += s * acc[f].w;
        }
        atomicAdd(reinterpret_cast<float4*>(&d_H[c * HW + hwb]), h);
    }
}

// ---------------- L2: out[b,c] += sum_hw |x|*H, 8 hw-chunks per batch -------
__global__ void __launch_bounds__(256) k_out(const float* __restrict__ x,
                                             float* __restrict__ out) {
    const int b = blockIdx.y;
    const int chunk = blockIdx.x;
    const int tx = threadIdx.x;
    const int hw0 = chunk * 512;
    float acc[10];
#pragma unroll
    for (int c = 0; c < 10; c++) acc[c] = 0.f;
#pragma unroll
    for (int k = 0; k < 2; k++) {
        const int hw = hw0 + k * 256 + tx;
        const float a = fabsf(x[b * HW + hw]);
#pragma unroll
        for (int c = 0; c < 10; c++) acc[c] += a * d_H[c * HW + hw];
    }
    __shared__ float red[10][256];
#pragma unroll
    for (int c = 0; c < 10; c++) red[c][tx] = acc[c];
    __syncthreads();
    for (int s = 128; s > 0; s >>= 1) {
        if (tx < s) {
#pragma unroll
            for (int c = 0; c < 10; c++) red[c][tx] += red[c][tx + s];
        }
        __syncthreads();
    }
    if (tx < 10) {
        float v = red[tx][0];
        if (chunk == 0) v += d_biasv[tx];
        atomicAdd(&out[b * 10 + tx], v);
    }
}

// ---------------- launch -----------------------------------------------------
extern "C" void kernel_launch(void* const* d_in, const int* in_sizes, int n_in,
                              void* d_out, int out_size) {
    const float* x    = (const float*)d_in[0];
    const float* w1r  = (const float*)d_in[1];
    const float* w1i  = (const float*)d_in[2];
    const float* w2r  = (const float*)d_in[3];
    const float* w2i  = (const float*)d_in[4];
    const float* fc1w = (const float*)d_in[5];
    const float* fc1b = (const float*)d_in[6];
    const float* fc2w = (const float*)d_in[7];
    const float* fc2b = (const float*)d_in[8];
    float* out = (float*)d_out;

    k_a2all<<<268, 256>>>(w1r, w1i, w2r, w2i, fc2w, fc1b, fc2b, out);  // 0
    k_g    <<<dim3(8, 64), 128>>>(fc1w, fc2w);                         // 1
    k_out  <<<dim3(8, 32), 256>>>(x, out);                             // 2
}

// round 16
// speedup vs baseline: 1.1372x; 1.0812x over previous
#include <cuda_runtime.h>
#include <math.h>

#define HW   4096
#define NC1  32
#define NC2  64
#define NFC1 512

// ---------------- scratch (static __device__, no allocation) ----------------
__device__ float  d_M1[NC1 * HW];                  // |FFT2(pad(w1))|     0.5 MB
__device__ float  d_A2[NC2 * HW];                  // layer-2 magnitude     1 MB
__device__ float  d_H[10 * HW];                    // fc2-collapsed       160 KB
__device__ float  d_biasv[10];                     // fc2b + fc2w@fc1b

// ---------------- L0 prep: M1 DFT + bias + zero H + zero out (R10 body) -----
__global__ void __launch_bounds__(256) k_prep(const float* __restrict__ w1r,
                                              const float* __restrict__ w1i,
                                              const float* __restrict__ fc2w,
                                              const float* __restrict__ fc1b,
                                              const float* __restrict__ fc2b,
                                              float* __restrict__ out) {
    __shared__ float twr[64], twi[64], wr[25], wi[25];
    const int bx = blockIdx.x;
    const int tx = threadIdx.x;
    if (bx < 512) {
        if (tx < 64) {
            float s, c;
            sincosf(-6.283185307179586f * (float)tx / 64.0f, &s, &c);
            twr[tx] = c; twi[tx] = s;
        }
        const int i = bx >> 4, tile = bx & 15;
        if (tx < 25) { wr[tx] = w1r[i * 25 + tx]; wi[tx] = w1i[i * 25 + tx]; }
        __syncthreads();
        const int hw = tile * 256 + tx;
        const int u = hw >> 6, v = hw & 63;
        float re = 0.f, im = 0.f;
#pragma unroll
        for (int a = 0; a < 5; a++)
#pragma unroll
            for (int b = 0; b < 5; b++) {
                const int idx = (u * a + v * b) & 63;
                const float tr = twr[idx], ti = twi[idx];
                const float r = wr[a * 5 + b], q = wi[a * 5 + b];
                re += r * tr - q * ti;
                im += r * ti + q * tr;
            }
        d_M1[i * HW + hw] = sqrtf(re * re + im * im);
    } else if (bx == 512) {
        const int w = tx >> 5, lane = tx & 31;
        for (int c = w; c < 10; c += 8) {
            float s = 0.f;
            for (int f = lane; f < NFC1; f += 32)
                s += fc2w[c * NFC1 + f] * fc1b[f];
#pragma unroll
            for (int off = 16; off > 0; off >>= 1)
                s += __shfl_down_sync(0xffffffffu, s, off);
            if (lane == 0) d_biasv[c] = s + fc2b[c];
        }
    } else if (bx < 523) {
        const int base = (bx - 513) * 4096;
#pragma unroll
        for (int k = 0; k < 16; k++) d_H[base + k * 256 + tx] = 0.f;
    } else {
        for (int i = tx; i < 320; i += 256) out[i] = 0.f;
    }
}

// ---------------- L1: A2 (R10 body) + PDL prologue/sync ---------------------
__global__ void __launch_bounds__(256) k_a2f(const float* __restrict__ w2r,
                                             const float* __restrict__ w2i) {
    __shared__ float2 Ts[8 * 320];
    __shared__ float twr[64], twi[64];
    const int tx = threadIdx.x;
    const int o = blockIdx.y;
    const int du = tx >> 6, v = tx & 63;
    const int u0 = blockIdx.x * 4 + du;
    // ---- prologue (independent of prep): twiddles + per-thread rotations ----
    if (tx < 64) {
        float s, c;
        sincosf(-6.283185307179586f * (float)tx / 64.0f, &s, &c);
        twr[tx] = c; twi[tx] = s;
    }
    __syncthreads();
    float tur[5], tui[5];
#pragma unroll
    for (int a = 0; a < 5; a++) {
        const int k = (u0 * a) & 63;
        tur[a] = twr[k]; tui[a] = twi[k];
    }
    // ---- wait for prep (M1) ----
    cudaGridDependencySynchronize();

    float re0 = 0.f, im0 = 0.f, re1 = 0.f, im1 = 0.f;
    float re2 = 0.f, im2 = 0.f, re3 = 0.f, im3 = 0.f;
    const int hwb = u0 * 64 + v;

    for (int c = 0; c < 4; c++) {
        __syncthreads();
        for (int i2 = tx; i2 < 8 * 320; i2 += 256) {
            const int ii = i2 / 320;
            const int r = i2 - ii * 320;
            const int a = r >> 6, vv = r & 63;
            const int oi = o * NC1 + c * 8 + ii;
            float re = 0.f, im = 0.f;
#pragma unroll
            for (int b = 0; b < 5; b++) {
                const int k = (vv * b) & 63;
                const float rr = w2r[oi * 25 + a * 5 + b];
                const float qq = w2i[oi * 25 + a * 5 + b];
                re += rr * twr[k] - qq * twi[k];
                im += rr * twi[k] + qq * twr[k];
            }
            Ts[i2] = make_float2(re, im);
        }
        __syncthreads();
#pragma unroll
        for (int ii = 0; ii < 8; ii++) {
            const int ig = c * 8 + ii;
            const float m0 = d_M1[ig * HW + hwb];
            const float m1 = d_M1[ig * HW + hwb + 1024];
            const float m2 = d_M1[ig * HW + hwb + 2048];
            const float m3 = d_M1[ig * HW + hwb + 3072];
            float kr0 = 0.f, ki0 = 0.f, kr1 = 0.f, ki1 = 0.f;
            float kr2 = 0.f, ki2 = 0.f, kr3 = 0.f, ki3 = 0.f;
#pragma unroll
            for (int a = 0; a < 5; a++) {
                const float2 tt = Ts[ii * 320 + a * 64 + v];
                const float pr = tur[a] * tt.x - tui[a] * tt.y;
                const float pi = tur[a] * tt.y + tui[a] * tt.x;
                kr0 += pr; ki0 += pi;
                switch (a & 3) {
                    case 0: kr1 += pr; ki1 += pi;
                            kr2 += pr; ki2 += pi;
                            kr3 += pr; ki3 += pi; break;
                    case 1: kr1 += pi; ki1 -= pr;
                            kr2 -= pr; ki2 -= pi;
                            kr3 -= pi; ki3 += pr; break;
                    case 2: kr1 -= pr; ki1 -= pi;
                            kr2 += pr; ki2 += pi;
                            kr3 -= pr; ki3 -= pi; break;
                    case 3: kr1 -= pi; ki1 += pr;
                            kr2 -= pr; ki2 -= pi;
                            kr3 += pi; ki3 -= pr; break;
                }
            }
            re0 += m0 * kr0; im0 += m0 * ki0;
            re1 += m1 * kr1; im1 += m1 * ki1;
            re2 += m2 * kr2; im2 += m2 * ki2;
            re3 += m3 * kr3; im3 += m3 * ki3;
        }
    }
    d_A2[o * HW + hwb]        = sqrtf(re0 * re0 + im0 * im0);
    d_A2[o * HW + hwb + 1024] = sqrtf(re1 * re1 + im1 * im1);
    d_A2[o * HW + hwb + 2048] = sqrtf(re2 * re2 + im2 * im2);
    d_A2[o * HW + hwb + 3072] = sqrtf(re3 * re3 + im3 * im3);
}

// ---------------- L2 (dominant): R10 body + PDL prologue/sync ---------------
__global__ void __launch_bounds__(128) k_g(const float* __restrict__ fc1w,
                                           const float* __restrict__ fc2w) {
    __shared__ float4 a2s[16 * 128];
    __shared__ float fc2s[10][8];
    const int t = threadIdx.x;
    const int tile = blockIdx.x;
    const int f0 = blockIdx.y * 8;
    // ---- prologue (independent of a2f): fc2 tile ----
    if (t < 80) {
        const int c = t >> 3, f = t & 7;
        fc2s[c][f] = fc2w[c * NFC1 + f0 + f];
    }
    // ---- wait for a2f (A2) ----
    cudaGridDependencySynchronize();

    const float4* __restrict__ a2g = (const float4*)d_A2;
    const float4* __restrict__ w = (const float4*)fc1w;

    float4 acc[8];
#pragma unroll
    for (int f = 0; f < 8; f++) acc[f] = make_float4(0.f, 0.f, 0.f, 0.f);

    for (int oc = 0; oc < 4; oc++) {
        __syncthreads();
        for (int idx = t; idx < 16 * 128; idx += 128) {
            const int o = idx >> 7, j = idx & 127;
            a2s[idx] = a2g[(oc * 16 + o) * 1024 + tile * 128 + j];
        }
        __syncthreads();
#pragma unroll
        for (int o = 0; o < 16; o++) {
            const float4 av = a2s[o * 128 + t];
            const size_t wb = (size_t)(oc * 16 + o) * 1024 + (size_t)tile * 128 + t;
#pragma unroll
            for (int f = 0; f < 8; f++) {
                const float4 wv = __ldcs(&w[(size_t)(f0 + f) * 65536 + wb]);
                acc[f].x += av.x * wv.x;
                acc[f].y += av.y * wv.y;
                acc[f].z += av.z * wv.z;
                acc[f].w += av.w * wv.w;
            }
        }
    }
    const int hwb = (tile * 128 + t) * 4;
#pragma unroll
    for (int c = 0; c < 10; c++) {
        float4 h = make_float4(0.f, 0.f, 0.f, 0.f);
#pragma unroll
        for (int f = 0; f < 8; f++) {
            const float s = fc2s[c][f];
            h.x += s * acc[f].x;
            h.y += s * acc[f].y;
            h.z += s * acc[f].z;
            h.w += s * acc[f].w;
        }
        atomicAdd(reinterpret_cast<float4*>(&d_H[c * HW + hwb]), h);
    }
}

// ---------------- L3: k_out (R10 body) + PDL prologue/sync ------------------
__global__ void __launch_bounds__(256) k_out(const float* __restrict__ x,
                                             float* __restrict__ out) {
    const int b = blockIdx.y;
    const int chunk = blockIdx.x;
    const int tx = threadIdx.x;
    const int hw0 = chunk * 512;
    // ---- prologue (independent of k_g): |x| loads ----
    float a0 = fabsf(x[b * HW + hw0 + tx]);
    float a1 = fabsf(x[b * HW + hw0 + 256 + tx]);
    // ---- wait for k_g (H) ----
    cudaGridDependencySynchronize();

    float acc[10];
#pragma unroll
    for (int c = 0; c < 10; c++)
        acc[c] = a0 * d_H[c * HW + hw0 + tx] + a1 * d_H[c * HW + hw0 + 256 + tx];
    __shared__ float red[10][256];
#pragma unroll
    for (int c = 0; c < 10; c++) red[c][tx] = acc[c];
    __syncthreads();
    for (int s = 128; s > 0; s >>= 1) {
        if (tx < s) {
#pragma unroll
            for (int c = 0; c < 10; c++) red[c][tx] += red[c][tx + s];
        }
        __syncthreads();
    }
    if (tx < 10) {
        float v = red[tx][0];
        if (chunk == 0) v += d_biasv[tx];
        atomicAdd(&out[b * 10 + tx], v);
    }
}

// ---------------- launch: PDL-chained ----------------------------------------
static void launch_pdl(void* fn, dim3 grid, dim3 block, void** args) {
    cudaLaunchConfig_t cfg = {};
    cfg.gridDim = grid;
    cfg.blockDim = block;
    cudaLaunchAttribute attr[1];
    attr[0].id = cudaLaunchAttributeProgrammaticStreamSerialization;
    attr[0].val.programmaticStreamSerializationAllowed = 1;
    cfg.attrs = attr;
    cfg.numAttrs = 1;
    cudaLaunchKernelExC(&cfg, fn, args);
}

extern "C" void kernel_launch(void* const* d_in, const int* in_sizes, int n_in,
                              void* d_out, int out_size) {
    const float* x    = (const float*)d_in[0];
    const float* w1r  = (const float*)d_in[1];
    const float* w1i  = (const float*)d_in[2];
    const float* w2r  = (const float*)d_in[3];
    const float* w2i  = (const float*)d_in[4];
    const float* fc1w = (const float*)d_in[5];
    const float* fc1b = (const float*)d_in[6];
    const float* fc2w = (const float*)d_in[7];
    const float* fc2b = (const float*)d_in[8];
    float* out = (float*)d_out;

    k_prep<<<524, 256>>>(w1r, w1i, fc2w, fc1b, fc2b, out);           // 0

    {   // a2f (PDL on prep)
        void* args[] = {(void*)&w2r, (void*)&w2i};
        launch_pdl((void*)k_a2f, dim3(4, 64), dim3(256), args);      // 1
    }
    {   // k_g (PDL on a2f)
        void* args[] = {(void*)&fc1w, (void*)&fc2w};
        launch_pdl((void*)k_g, dim3(8, 64), dim3(128), args);        // 2
    }
    {   // k_out (PDL on k_g)
        void* args[] = {(void*)&x, (void*)&out};
        launch_pdl((void*)k_out, dim3(8, 32), dim3(256), args);      // 3
    }
}